// round 9
// baseline (speedup 1.0000x reference)
#include <cuda_runtime.h>

#define N_NODES 50000
#define N_EDGES 800000
#define IN_CH   64
#define HID_CH  128

#define NPB 8            // nodes per fused block (1 per warp)
#define CAP 96           // bucket capacity (deg ~ Poisson(16); P(>96) ~ 0)
#define NPAD (N_NODES + 64)

// Scratch (device globals; no runtime allocation allowed)
__device__ int g_cnt[NPAD];             // per-node degree
__device__ int g_esrc[NPAD * CAP];      // fixed-capacity buckets (~19MB)

// packed f32x2 FMA: d = a*b + d
__device__ __forceinline__ void fma2(unsigned long long& d,
                                     unsigned long long a,
                                     unsigned long long b) {
    asm("fma.rn.f32x2 %0, %1, %2, %0;" : "+l"(d) : "l"(a), "l"(b));
}

// ---------------------------------------------------------------------------
// 1) zero degree counters (200KB)
// ---------------------------------------------------------------------------
__global__ void k_zero() {
    int i = blockIdx.x * blockDim.x + threadIdx.x;
    if (i < NPAD) g_cnt[i] = 0;
}

// ---------------------------------------------------------------------------
// 2) bucket edges by dst; 2 edges per thread via int2 loads
// ---------------------------------------------------------------------------
__global__ void k_bucket(const int* __restrict__ ei) {
    int t = blockIdx.x * blockDim.x + threadIdx.x;
    int e = t * 2;
    if (e >= N_EDGES) return;
    int2 s2 = *reinterpret_cast<const int2*>(ei + e);
    int2 d2 = *reinterpret_cast<const int2*>(ei + N_EDGES + e);
    if ((unsigned)s2.x < N_NODES && (unsigned)d2.x < N_NODES) {
        int pos = atomicAdd(&g_cnt[d2.x], 1);
        if (pos < CAP) g_esrc[d2.x * CAP + pos] = s2.x;
    }
    if ((unsigned)s2.y < N_NODES && (unsigned)d2.y < N_NODES) {
        int pos = atomicAdd(&g_cnt[d2.y], 1);
        if (pos < CAP) g_esrc[d2.y * CAP + pos] = s2.y;
    }
}

// ---------------------------------------------------------------------------
// 3) fused aggregate (mean) + GEMM.
// Block = 256 threads = 8 warps, 8 nodes; warp w owns node block*8+w.
// Phase A: warp loads <=32 edge indices in ONE coalesced LDG, then a fully
//   unrolled 16-pair predicated loop: lanes 0-15 gather even edges' rows
//   (c=lane&15 float4 chunk), lanes 16-31 odd edges. All gathers independent
//   -> ~16 loads in flight per warp. Mean -> smem.
// Phase B: out[n][o] = mean[n] . W[o] via packed f32x2 FMAs (W loaded into
//   registers after phase A to keep gather-phase register pressure low).
// ---------------------------------------------------------------------------
__global__ void __launch_bounds__(256, 2)
k_fused(const float* __restrict__ x, const float* __restrict__ W,
        float* __restrict__ out) {
    __shared__ float s_mean[NPB * IN_CH];

    const int tid   = threadIdx.x;
    const int node0 = blockIdx.x * NPB;
    const int wid   = tid >> 5;
    const int lane  = tid & 31;
    const int c     = lane & 15;   // float4 chunk within the 64-ch row
    const int half  = lane >> 4;   // edge parity

    const float4* x4 = reinterpret_cast<const float4*>(x);

    // -------- Phase A: one node per warp --------
    {
        const int node = node0 + wid;             // < N_NODES (grid exact) + pad
        const int cnt  = g_cnt[node];
        const int m    = min(cnt, CAP);
        const int base = node * CAP;

        float4 acc = make_float4(0.f, 0.f, 0.f, 0.f);
        for (int b = 0; b < m; b += 32) {         // single iteration for deg<=32
            const int chunk = min(m - b, 32);
            int idx = (lane < chunk) ? g_esrc[base + b + lane] : 0;
            #pragma unroll
            for (int j = 0; j < 16; j++) {
                const int i = 2 * j + half;
                int src = __shfl_sync(0xffffffffu, idx, i & 31);
                if (i < chunk) {
                    float4 v = __ldg(x4 + (size_t)src * (IN_CH / 4) + c);
                    acc.x += v.x; acc.y += v.y; acc.z += v.z; acc.w += v.w;
                }
            }
        }
        acc.x += __shfl_down_sync(0xffffffffu, acc.x, 16);
        acc.y += __shfl_down_sync(0xffffffffu, acc.y, 16);
        acc.z += __shfl_down_sync(0xffffffffu, acc.z, 16);
        acc.w += __shfl_down_sync(0xffffffffu, acc.w, 16);

        if (half == 0) {
            float scale = 1.0f / fmaxf((float)cnt, 1.0f);
            float4 mm = make_float4(acc.x * scale, acc.y * scale,
                                    acc.z * scale, acc.w * scale);
            *reinterpret_cast<float4*>(&s_mean[wid * IN_CH + c * 4]) = mm;
        }
    }

    // W row -> 32 packed f32x2 registers (loaded after the gather phase)
    const int o = tid & 127;
    unsigned long long w2[IN_CH / 2];
    {
        const ulonglong2* Wrow = reinterpret_cast<const ulonglong2*>(W) + o * (IN_CH / 4);
        #pragma unroll
        for (int k = 0; k < IN_CH / 4; k++) {
            ulonglong2 t = __ldg(Wrow + k);
            w2[2 * k + 0] = t.x;
            w2[2 * k + 1] = t.y;
        }
    }
    __syncthreads();

    // -------- Phase B: GEMM (thread t: o = t&127; nodes (t>>7)*4 + 0..3) ----
    const int nhalf = tid >> 7;
    #pragma unroll
    for (int nn = 0; nn < NPB / 2; nn++) {
        const int n = nhalf * (NPB / 2) + nn;
        unsigned long long acc2 = 0ull;
        const ulonglong2* mrow = reinterpret_cast<const ulonglong2*>(s_mean + n * IN_CH);
        #pragma unroll
        for (int k = 0; k < IN_CH / 4; k++) {
            ulonglong2 mv = mrow[k];      // LDS.128 -> two packed f32x2
            fma2(acc2, mv.x, w2[2 * k + 0]);
            fma2(acc2, mv.y, w2[2 * k + 1]);
        }
        float lo, hi;
        asm("mov.b64 {%0, %1}, %2;" : "=f"(lo), "=f"(hi) : "l"(acc2));
        out[(size_t)(node0 + n) * HID_CH + o] = lo + hi;
    }
}

// ---------------------------------------------------------------------------
extern "C" void kernel_launch(void* const* d_in, const int* in_sizes, int n_in,
                              void* d_out, int out_size) {
    const float* x  = (const float*)d_in[0];      // [50000, 64] fp32
    const int*   ei = (const int*)d_in[1];        // [2, 800000] int32
    const float* W  = (const float*)d_in[2];      // [128, 64] fp32
    float* out = (float*)d_out;                   // [50000, 128] fp32

    k_zero<<<(NPAD + 255) / 256, 256>>>();
    k_bucket<<<(N_EDGES / 2 + 255) / 256, 256>>>(ei);
    k_fused<<<N_NODES / NPB, 256>>>(x, W, out);   // 50000/8 = 6250 exact
}

// round 10
// speedup vs baseline: 1.7518x; 1.7518x over previous
#include <cuda_runtime.h>
#include <cstdint>

#define N_NODES 50000
#define N_EDGES 800000
#define IN_CH   64
#define HID_CH  128

#define NPB 32           // nodes per fused block (4 per warp)
#define CAP 96           // bucket capacity (deg ~ Poisson(16))
#define NPAD (N_NODES + NPB)
#define STAGE 8          // edges per cp.async stage

// Scratch (device globals; no runtime allocation allowed)
__device__ int g_cnt[NPAD];
__device__ int g_esrc[NPAD * CAP];

// packed f32x2 FMA: d = a*b + d
__device__ __forceinline__ void fma2(unsigned long long& d,
                                     unsigned long long a,
                                     unsigned long long b) {
    asm("fma.rn.f32x2 %0, %1, %2, %0;" : "+l"(d) : "l"(a), "l"(b));
}

__device__ __forceinline__ void cp16(uint32_t smem_addr, const void* gptr) {
    asm volatile("cp.async.cg.shared.global [%0], [%1], 16;"
                 :: "r"(smem_addr), "l"(gptr) : "memory");
}
__device__ __forceinline__ void cp_commit() {
    asm volatile("cp.async.commit_group;" ::: "memory");
}
template <int N>
__device__ __forceinline__ void cp_wait() {
    asm volatile("cp.async.wait_group %0;" :: "n"(N) : "memory");
}

// ---------------------------------------------------------------------------
__global__ void k_zero() {
    int i = blockIdx.x * blockDim.x + threadIdx.x;
    if (i < NPAD) g_cnt[i] = 0;
}

__global__ void k_bucket(const int* __restrict__ ei) {
    int e = blockIdx.x * blockDim.x + threadIdx.x;
    if (e >= N_EDGES) return;
    int src = ei[e];
    int dst = ei[N_EDGES + e];
    if ((unsigned)src >= N_NODES || (unsigned)dst >= N_NODES) return;
    int pos = atomicAdd(&g_cnt[dst], 1);
    if (pos < CAP) g_esrc[dst * CAP + pos] = src;
}

// ---------------------------------------------------------------------------
// fused aggregate (mean) + GEMM.
// Block = 256 thr = 8 warps, 32 nodes (4/warp).
// Phase A: per warp, edges staged 8-at-a-time into smem via cp.async.cg
//   (no LDG outstanding cap, no live registers), double-buffered: stage s+1
//   in flight while stage s is reduced from smem. Lanes 0-15 own even edge
//   slots, 16-31 odd; c = lane&15 is the float4 chunk. Mean -> s_mean.
// Phase B: out[n][o] = mean[n].W[o] via packed f32x2 FMAs.
// ---------------------------------------------------------------------------
__global__ void __launch_bounds__(256, 2)
k_fused(const float* __restrict__ x, const float* __restrict__ W,
        float* __restrict__ out) {
    __shared__ float s_buf[8][2][STAGE][IN_CH];   // 32 KB staging
    __shared__ float s_mean[NPB * IN_CH];         // 8 KB

    const int tid   = threadIdx.x;
    const int node0 = blockIdx.x * NPB;
    const int wid   = tid >> 5;
    const int lane  = tid & 31;
    const int c     = lane & 15;
    const int half  = lane >> 4;

    const float4* x4 = reinterpret_cast<const float4*>(x);

    float4 acc0 = {0,0,0,0}, acc1 = {0,0,0,0}, acc2 = {0,0,0,0}, acc3 = {0,0,0,0};

    // pipeline state (warp-uniform)
    int pk = -1, pcnt = 0, pbuf = 0, p = 0;

    #define REDUCE_PENDING()                                                   \
        do {                                                                   \
            cp_wait<1>();                                                      \
            __syncwarp();                                                      \
            float4 part = {0,0,0,0};                                           \
            _Pragma("unroll")                                                  \
            for (int r = 0; r < 4; r++) {                                      \
                int slot = r * 2 + half;                                       \
                if (slot < pcnt) {                                             \
                    float4 v = *reinterpret_cast<const float4*>(               \
                        &s_buf[wid][pbuf][slot][c * 4]);                       \
                    part.x += v.x; part.y += v.y;                              \
                    part.z += v.z; part.w += v.w;                              \
                }                                                              \
            }                                                                  \
            if      (pk == 0) { acc0.x+=part.x; acc0.y+=part.y; acc0.z+=part.z; acc0.w+=part.w; } \
            else if (pk == 1) { acc1.x+=part.x; acc1.y+=part.y; acc1.z+=part.z; acc1.w+=part.w; } \
            else if (pk == 2) { acc2.x+=part.x; acc2.y+=part.y; acc2.z+=part.z; acc2.w+=part.w; } \
            else              { acc3.x+=part.x; acc3.y+=part.y; acc3.z+=part.z; acc3.w+=part.w; } \
        } while (0)

    for (int k = 0; k < 4; k++) {
        const int node = node0 + wid * 4 + k;     // < NPAD (padded, cnt=0)
        const int cnt  = g_cnt[node];
        const int m    = min(cnt, CAP);
        const int base = node * CAP;

        for (int w = 0; w < m; w += 32) {
            const int mw  = min(m - w, 32);
            int idx = ((w + lane) < m) ? g_esrc[base + w + lane] : 0;
            const int nst = (mw + STAGE - 1) / STAGE;

            for (int s = 0; s < nst; s++) {
                __syncwarp();  // WAR: buffer p was read 2 stages ago
                // issue stage s into buffer p
                #pragma unroll
                for (int r = 0; r < 4; r++) {
                    const int slot = r * 2 + half;
                    const int eL   = s * STAGE + slot;     // <= 31
                    int src = __shfl_sync(0xffffffffu, idx, eL);
                    if (eL < mw) {
                        uint32_t dstw = (uint32_t)__cvta_generic_to_shared(
                            &s_buf[wid][p][slot][c * 4]);
                        cp16(dstw, x4 + (size_t)src * (IN_CH / 4) + c);
                    }
                }
                cp_commit();

                if (pk >= 0) REDUCE_PENDING();

                pk = k; pcnt = min(mw - s * STAGE, STAGE); pbuf = p; p ^= 1;
            }
        }
    }
    if (pk >= 0) {
        pcnt = pcnt; // keep
        cp_wait<0>();
        __syncwarp();
        float4 part = {0,0,0,0};
        #pragma unroll
        for (int r = 0; r < 4; r++) {
            int slot = r * 2 + half;
            if (slot < pcnt) {
                float4 v = *reinterpret_cast<const float4*>(&s_buf[wid][pbuf][slot][c * 4]);
                part.x += v.x; part.y += v.y; part.z += v.z; part.w += v.w;
            }
        }
        if      (pk == 0) { acc0.x+=part.x; acc0.y+=part.y; acc0.z+=part.z; acc0.w+=part.w; }
        else if (pk == 1) { acc1.x+=part.x; acc1.y+=part.y; acc1.z+=part.z; acc1.w+=part.w; }
        else if (pk == 2) { acc2.x+=part.x; acc2.y+=part.y; acc2.z+=part.z; acc2.w+=part.w; }
        else              { acc3.x+=part.x; acc3.y+=part.y; acc3.z+=part.z; acc3.w+=part.w; }
    }

    // finalize: cross-half reduce + mean -> smem
    #define FINALIZE(A, K)                                                     \
        do {                                                                   \
            A.x += __shfl_down_sync(0xffffffffu, A.x, 16);                     \
            A.y += __shfl_down_sync(0xffffffffu, A.y, 16);                     \
            A.z += __shfl_down_sync(0xffffffffu, A.z, 16);                     \
            A.w += __shfl_down_sync(0xffffffffu, A.w, 16);                     \
            if (half == 0) {                                                   \
                int nd = node0 + wid * 4 + (K);                                \
                float sc = 1.0f / fmaxf((float)g_cnt[nd], 1.0f);               \
                float4 mm = make_float4(A.x*sc, A.y*sc, A.z*sc, A.w*sc);       \
                *reinterpret_cast<float4*>(                                    \
                    &s_mean[(wid * 4 + (K)) * IN_CH + c * 4]) = mm;            \
            }                                                                  \
        } while (0)
    FINALIZE(acc0, 0);
    FINALIZE(acc1, 1);
    FINALIZE(acc2, 2);
    FINALIZE(acc3, 3);

    // W row -> 32 packed f32x2 registers (after gather phase)
    const int o = tid & 127;
    unsigned long long w2[IN_CH / 2];
    {
        const ulonglong2* Wrow = reinterpret_cast<const ulonglong2*>(W) + o * (IN_CH / 4);
        #pragma unroll
        for (int kk = 0; kk < IN_CH / 4; kk++) {
            ulonglong2 t = __ldg(Wrow + kk);
            w2[2 * kk + 0] = t.x;
            w2[2 * kk + 1] = t.y;
        }
    }
    __syncthreads();

    // Phase B: GEMM
    const int nhalf = tid >> 7;
    #pragma unroll 2
    for (int nn = 0; nn < NPB / 2; nn++) {
        const int n = nhalf * (NPB / 2) + nn;
        unsigned long long a2 = 0ull;
        const ulonglong2* mrow = reinterpret_cast<const ulonglong2*>(s_mean + n * IN_CH);
        #pragma unroll
        for (int kk = 0; kk < IN_CH / 4; kk++) {
            ulonglong2 mv = mrow[kk];
            fma2(a2, mv.x, w2[2 * kk + 0]);
            fma2(a2, mv.y, w2[2 * kk + 1]);
        }
        float lo, hi;
        asm("mov.b64 {%0, %1}, %2;" : "=f"(lo), "=f"(hi) : "l"(a2));
        const int node = node0 + n;
        if (node < N_NODES) {
            out[(size_t)node * HID_CH + o] = lo + hi;
        }
    }
}

// ---------------------------------------------------------------------------
extern "C" void kernel_launch(void* const* d_in, const int* in_sizes, int n_in,
                              void* d_out, int out_size) {
    const float* x  = (const float*)d_in[0];      // [50000, 64] fp32
    const int*   ei = (const int*)d_in[1];        // [2, 800000] int32
    const float* W  = (const float*)d_in[2];      // [128, 64] fp32
    float* out = (float*)d_out;                   // [50000, 128] fp32

    k_zero<<<(NPAD + 255) / 256, 256>>>();
    k_bucket<<<(N_EDGES + 255) / 256, 256>>>(ei);
    k_fused<<<(N_NODES + NPB - 1) / NPB, 256>>>(x, W, out);
}